// round 2
// baseline (speedup 1.0000x reference)
#include <cuda_runtime.h>

#define NUMLAB 670000
#define Bn 128
#define Cn 65536
#define Mn 16
#define Hn 512
#define Kn 200
#define KMn 3200   // Kn*Mn

// ---- scratch (no allocations allowed) ----
__device__ int   g_topk_idx[Bn * Kn];
__device__ float g_topk_score[Bn * Kn];
__device__ int   g_cands[Bn * KMn];
__device__ float g_cscores[Bn * KMn];

// monotone float->uint key: descending float == descending key
__device__ __forceinline__ unsigned fkey(float x) {
    unsigned u = __float_as_uint(x);
    return (u & 0x80000000u) ? ~u : (u | 0x80000000u);
}

// ============================================================
// Kernel 1: per-row exact top-200 (value desc, index asc ties)
// 4x 8-bit radix-select passes + 1 collect pass.
// One block (1024 thr) per row.
// ============================================================
__global__ void __launch_bounds__(1024) topk_kernel(const float* __restrict__ logits) {
    const int row = blockIdx.x;
    const float*  rp  = logits + (size_t)row * Cn;
    const float4* rp4 = (const float4*)rp;

    __shared__ unsigned s_hist[32 * 256];   // warp-private histograms
    __shared__ unsigned s_red[256];
    __shared__ unsigned s_prefix;
    __shared__ int      s_kneed;
    __shared__ unsigned s_bu[1024];
    __shared__ int      s_bi[1024];
    __shared__ int      s_cnt;

    const int tid = threadIdx.x;
    const int wid = tid >> 5;
    if (tid == 0) { s_kneed = Kn; s_prefix = 0u; s_cnt = 0; }
    __syncthreads();

    for (int shift = 24; shift >= 0; shift -= 8) {
        for (int i = tid; i < 32 * 256; i += 1024) s_hist[i] = 0u;
        __syncthreads();
        const unsigned pref = s_prefix;
        const unsigned mhi  = (shift == 24) ? 0u : (0xFFFFFFFFu << (shift + 8));
        unsigned* myh = &s_hist[wid * 256];
        for (int i = tid; i < Cn / 4; i += 1024) {
            float4 v = rp4[i];
            unsigned u;
            u = fkey(v.x); if ((u & mhi) == pref) atomicAdd(&myh[(u >> shift) & 255], 1u);
            u = fkey(v.y); if ((u & mhi) == pref) atomicAdd(&myh[(u >> shift) & 255], 1u);
            u = fkey(v.z); if ((u & mhi) == pref) atomicAdd(&myh[(u >> shift) & 255], 1u);
            u = fkey(v.w); if ((u & mhi) == pref) atomicAdd(&myh[(u >> shift) & 255], 1u);
        }
        __syncthreads();
        for (int b = tid; b < 256; b += 1024) {
            unsigned s = 0;
            #pragma unroll
            for (int w = 0; w < 32; w++) s += s_hist[w * 256 + b];
            s_red[b] = s;
        }
        __syncthreads();
        if (tid == 0) {
            int kneed = s_kneed;
            int cum = 0;
            int b = 255;
            for (; b > 0; b--) {
                int c = (int)s_red[b];
                if (cum + c >= kneed) break;
                cum += c;
            }
            s_kneed  = kneed - cum;
            s_prefix = pref | ((unsigned)b << shift);
        }
        __syncthreads();
    }

    const unsigned T = s_prefix;   // exact 200th-largest key
    // collect all elements >= T (typically ~200, +ties)
    for (int i = tid; i < Cn / 4; i += 1024) {
        float4 v = rp4[i];
        float vals[4] = {v.x, v.y, v.z, v.w};
        #pragma unroll
        for (int t = 0; t < 4; t++) {
            unsigned u = fkey(vals[t]);
            if (u >= T) {
                int p = atomicAdd(&s_cnt, 1);
                if (p < 1024) { s_bu[p] = u; s_bi[p] = i * 4 + t; }
            }
        }
    }
    __syncthreads();
    const int m = min(s_cnt, 1024);
    // rank-select: rank = #{j : u_j > u_i or (u_j==u_i and idx_j < idx_i)}
    for (int i = tid; i < m; i += 1024) {
        unsigned ui = s_bu[i];
        int xi = s_bi[i];
        int r = 0;
        for (int j = 0; j < m; j++) {
            unsigned uj = s_bu[j];
            if (uj > ui || (uj == ui && s_bi[j] < xi)) r++;
        }
        if (r < Kn) {
            float v = rp[xi];
            g_topk_idx[row * Kn + r]   = xi;
            g_topk_score[row * Kn + r] = 1.f / (1.f + __expf(-v));
        }
    }
}

// ============================================================
// Kernel 2: expand clusters (k=200 -> 3200 cands) + stable
// pad-compaction (valid entries keep order, pads at the end).
// Writes cands (as float) to out[0 : B*KM).
// ============================================================
__global__ void __launch_bounds__(1024) expand_kernel(const int* __restrict__ clusters,
                                                      float* __restrict__ out) {
    const int row = blockIdx.x;
    const int tid = threadIdx.x;
    __shared__ int s_scan[1024];

    int cand[4];
    int valid[4];
    float sc = 0.f;
    const int base = tid * 4;
    int nv = 0;
    if (base < KMn) {
        const int j = base >> 4;                 // 4 | 16 => same topk slot for all 4
        const int idx = min(max(g_topk_idx[row * Kn + j], 0), Cn - 1);
        sc = g_topk_score[row * Kn + j];
        const int mb = base & 15;
        #pragma unroll
        for (int t = 0; t < 4; t++) {
            int c = clusters[(size_t)idx * Mn + mb + t];
            cand[t]  = c;
            valid[t] = (c != NUMLAB);
            nv += valid[t];
        }
    }
    s_scan[tid] = nv;
    __syncthreads();
    for (int off = 1; off < 1024; off <<= 1) {
        int v = (tid >= off) ? s_scan[tid - off] : 0;
        __syncthreads();
        s_scan[tid] += v;
        __syncthreads();
    }
    const int total = s_scan[1023];
    const int excl  = s_scan[tid] - nv;

    if (base < KMn) {
        int vb = excl;  // valids strictly before current element
        #pragma unroll
        for (int t = 0; t < 4; t++) {
            int pos;
            if (valid[t]) { pos = vb; vb++; }
            else          { pos = total + (base + t) - vb; }
            g_cands[row * KMn + pos]   = cand[t];
            g_cscores[row * KMn + pos] = valid[t] ? sc : 0.f;
            out[(size_t)row * KMn + pos] = (float)cand[t];
        }
    }
}

// ============================================================
// Kernel 3: gather embeddings + dot with h_c, sigmoid, outputs.
// Warp per candidate (4 per warp), h_c row in smem.
// ============================================================
__global__ void __launch_bounds__(256) score_kernel(const float* __restrict__ h_c,
                                                    const float* __restrict__ table,
                                                    float* __restrict__ out) {
    const int row = blockIdx.y;
    __shared__ float sh[Hn];
    for (int i = threadIdx.x; i < Hn; i += 256) sh[i] = h_c[(size_t)row * Hn + i];
    __syncthreads();

    const int warp = threadIdx.x >> 5;
    const int lane = threadIdx.x & 31;
    const int c0 = blockIdx.x * 32 + warp * 4;
    const float4* hv = (const float4*)sh;

    for (int t = 0; t < 4; t++) {
        const int c = c0 + t;
        int label = g_cands[row * KMn + c];
        label = min(max(label, 0), NUMLAB);
        const float4* er = (const float4*)(table + (size_t)label * Hn);
        float acc = 0.f;
        #pragma unroll
        for (int i = 0; i < 4; i++) {
            float4 e = er[lane + i * 32];
            float4 h = hv[lane + i * 32];
            acc += e.x * h.x;
            acc += e.y * h.y;
            acc += e.z * h.z;
            acc += e.w * h.w;
        }
        #pragma unroll
        for (int off = 16; off; off >>= 1)
            acc += __shfl_xor_sync(0xffffffffu, acc, off);
        if (lane == 0) {
            float s = (acc == 0.f) ? 0.f : (1.f / (1.f + __expf(-acc)));
            out[(size_t)Bn * KMn     + (size_t)row * KMn + c] = s;
            out[(size_t)Bn * KMn * 2 + (size_t)row * KMn + c] = s * g_cscores[row * KMn + c];
        }
    }
}

extern "C" void kernel_launch(void* const* d_in, const int* in_sizes, int n_in,
                              void* d_out, int out_size) {
    // Bind inputs by element count (robust to metadata ordering):
    //   meta_logits  128*65536   = 8388608  f32
    //   h_c          128*512     = 65536    f32
    //   embed_table  670001*512  = 343040512 f32
    //   label_clusters 65536*16  = 1048576  i32 (jax x64 disabled -> int32)
    const float* meta = nullptr;
    const float* hc = nullptr;
    const float* table = nullptr;
    const int* clusters = nullptr;
    for (int i = 0; i < n_in; i++) {
        switch (in_sizes[i]) {
            case 8388608:   meta     = (const float*)d_in[i]; break;
            case 65536:     hc       = (const float*)d_in[i]; break;
            case 343040512: table    = (const float*)d_in[i]; break;
            case 1048576:   clusters = (const int*)d_in[i];   break;
            default: break; // topk scalar etc.
        }
    }
    float* out = (float*)d_out; // 3 * 128 * 3200 f32: [cands | cand_scores | product]

    topk_kernel<<<Bn, 1024>>>(meta);
    expand_kernel<<<Bn, 1024>>>(clusters, out);
    dim3 g3(KMn / 32, Bn);
    score_kernel<<<g3, 256>>>(hc, table, out);
}

// round 3
// speedup vs baseline: 1.1422x; 1.1422x over previous
#include <cuda_runtime.h>

#define NUMLAB 670000
#define Bn 128
#define Cn 65536
#define Mn 16
#define Hn 512
#define Kn 200
#define KMn 3200   // Kn*Mn
#define CAP 3072   // collect buffer capacity

// ---- scratch (no allocations allowed) ----
__device__ int   g_topk_idx[Bn * Kn];
__device__ float g_topk_score[Bn * Kn];
__device__ int   g_cands[Bn * KMn];
__device__ float g_cscores[Bn * KMn];

// monotone float->uint key: descending float == descending key
__device__ __forceinline__ unsigned fkey(float x) {
    unsigned u = __float_as_uint(x);
    return (u & 0x80000000u) ? ~u : (u | 0x80000000u);
}

// ============================================================
// Kernel 1: per-row exact top-200 (value desc, index asc ties).
// Fast path: single scan collecting all elements >= fixed
// threshold (raw logit 2.5 — for ~N(0,1) rows this yields
// ~400 survivors >> 200), then exact O(m^2) rank-select in smem.
// Fallback (block-uniform, data-independent trigger): in-kernel
// 4x8-bit radix select with a single 256-bin histogram, then
// re-collect at the exact threshold. Guarantees correctness for
// arbitrary inputs.
// ============================================================
__global__ void __launch_bounds__(1024) topk_kernel(const float* __restrict__ logits) {
    const int row = blockIdx.x;
    const float*  rp  = logits + (size_t)row * Cn;
    const float4* rp4 = (const float4*)rp;

    __shared__ unsigned s_bu[CAP];
    __shared__ int      s_bi[CAP];
    __shared__ int      s_cnt;
    __shared__ unsigned s_red[256];
    __shared__ unsigned s_prefix;
    __shared__ int      s_kneed;

    const int tid = threadIdx.x;
    if (tid == 0) { s_cnt = 0; s_prefix = 0u; s_kneed = Kn; }
    __syncthreads();

    // ---- fast path: one streaming scan with fixed threshold ----
    const unsigned T0 = fkey(2.5f);
    for (int i = tid; i < Cn / 4; i += 1024) {
        float4 v = rp4[i];
        float vals[4] = {v.x, v.y, v.z, v.w};
        #pragma unroll
        for (int t = 0; t < 4; t++) {
            unsigned u = fkey(vals[t]);
            if (u >= T0) {
                int p = atomicAdd(&s_cnt, 1);
                if (p < CAP) { s_bu[p] = u; s_bi[p] = i * 4 + t; }
            }
        }
    }
    __syncthreads();
    int m = s_cnt;

    if (m < Kn || m > CAP) {
        // ---- fallback: exact radix select of the Kn-th largest key ----
        for (int shift = 24; shift >= 0; shift -= 8) {
            for (int b = tid; b < 256; b += 1024) s_red[b] = 0u;
            __syncthreads();
            const unsigned pref = s_prefix;
            const unsigned mhi  = (shift == 24) ? 0u : (0xFFFFFFFFu << (shift + 8));
            for (int i = tid; i < Cn / 4; i += 1024) {
                float4 v = rp4[i];
                float vals[4] = {v.x, v.y, v.z, v.w};
                #pragma unroll
                for (int t = 0; t < 4; t++) {
                    unsigned u = fkey(vals[t]);
                    if ((u & mhi) == pref) atomicAdd(&s_red[(u >> shift) & 255], 1u);
                }
            }
            __syncthreads();
            if (tid == 0) {
                int kneed = s_kneed;
                int cum = 0;
                int b = 255;
                for (; b > 0; b--) {
                    int c = (int)s_red[b];
                    if (cum + c >= kneed) break;
                    cum += c;
                }
                s_kneed  = kneed - cum;
                s_prefix = pref | ((unsigned)b << shift);
            }
            __syncthreads();
        }
        const unsigned T = s_prefix;   // exact Kn-th largest key
        if (tid == 0) s_cnt = 0;
        __syncthreads();
        for (int i = tid; i < Cn / 4; i += 1024) {
            float4 v = rp4[i];
            float vals[4] = {v.x, v.y, v.z, v.w};
            #pragma unroll
            for (int t = 0; t < 4; t++) {
                unsigned u = fkey(vals[t]);
                if (u >= T) {
                    int p = atomicAdd(&s_cnt, 1);
                    if (p < CAP) { s_bu[p] = u; s_bi[p] = i * 4 + t; }
                }
            }
        }
        __syncthreads();
        m = min(s_cnt, CAP);
    } else {
        m = min(m, CAP);
    }

    // ---- exact rank-select over m survivors ----
    // rank = #{j : u_j > u_i or (u_j == u_i and idx_j < idx_i)}
    for (int i = tid; i < m; i += 1024) {
        const unsigned ui = s_bu[i];
        const int xi = s_bi[i];
        int r = 0;
        for (int j = 0; j < m; j++) {
            const unsigned uj = s_bu[j];
            if (uj > ui || (uj == ui && s_bi[j] < xi)) r++;
        }
        if (r < Kn) {
            float v = rp[xi];
            g_topk_idx[row * Kn + r]   = xi;
            g_topk_score[row * Kn + r] = 1.f / (1.f + __expf(-v));
        }
    }
}

// ============================================================
// Kernel 2: expand clusters (k=200 -> 3200 cands) + stable
// pad-compaction (valid entries keep order, pads at the end).
// Writes cands (as float) to out[0 : B*KM).
// ============================================================
__global__ void __launch_bounds__(1024) expand_kernel(const int* __restrict__ clusters,
                                                      float* __restrict__ out) {
    const int row = blockIdx.x;
    const int tid = threadIdx.x;
    __shared__ int s_scan[1024];

    int cand[4];
    int valid[4];
    float sc = 0.f;
    const int base = tid * 4;
    int nv = 0;
    if (base < KMn) {
        const int j = base >> 4;                 // 4 | 16 => same topk slot for all 4
        const int idx = min(max(g_topk_idx[row * Kn + j], 0), Cn - 1);
        sc = g_topk_score[row * Kn + j];
        const int mb = base & 15;
        #pragma unroll
        for (int t = 0; t < 4; t++) {
            int c = clusters[(size_t)idx * Mn + mb + t];
            cand[t]  = c;
            valid[t] = (c != NUMLAB);
            nv += valid[t];
        }
    }
    s_scan[tid] = nv;
    __syncthreads();
    for (int off = 1; off < 1024; off <<= 1) {
        int v = (tid >= off) ? s_scan[tid - off] : 0;
        __syncthreads();
        s_scan[tid] += v;
        __syncthreads();
    }
    const int total = s_scan[1023];
    const int excl  = s_scan[tid] - nv;

    if (base < KMn) {
        int vb = excl;  // valids strictly before current element
        #pragma unroll
        for (int t = 0; t < 4; t++) {
            int pos;
            if (valid[t]) { pos = vb; vb++; }
            else          { pos = total + (base + t) - vb; }
            g_cands[row * KMn + pos]   = cand[t];
            g_cscores[row * KMn + pos] = valid[t] ? sc : 0.f;
            out[(size_t)row * KMn + pos] = (float)cand[t];
        }
    }
}

// ============================================================
// Kernel 3: gather embeddings + dot with h_c, sigmoid, outputs.
// Warp per candidate (4 per warp), h_c row in smem.
// ============================================================
__global__ void __launch_bounds__(256) score_kernel(const float* __restrict__ h_c,
                                                    const float* __restrict__ table,
                                                    float* __restrict__ out) {
    const int row = blockIdx.y;
    __shared__ float sh[Hn];
    for (int i = threadIdx.x; i < Hn; i += 256) sh[i] = h_c[(size_t)row * Hn + i];
    __syncthreads();

    const int warp = threadIdx.x >> 5;
    const int lane = threadIdx.x & 31;
    const int c0 = blockIdx.x * 32 + warp * 4;
    const float4* hv = (const float4*)sh;

    for (int t = 0; t < 4; t++) {
        const int c = c0 + t;
        int label = g_cands[row * KMn + c];
        label = min(max(label, 0), NUMLAB);
        const float4* er = (const float4*)(table + (size_t)label * Hn);
        float acc = 0.f;
        #pragma unroll
        for (int i = 0; i < 4; i++) {
            float4 e = er[lane + i * 32];
            float4 h = hv[lane + i * 32];
            acc += e.x * h.x;
            acc += e.y * h.y;
            acc += e.z * h.z;
            acc += e.w * h.w;
        }
        #pragma unroll
        for (int off = 16; off; off >>= 1)
            acc += __shfl_xor_sync(0xffffffffu, acc, off);
        if (lane == 0) {
            float s = (acc == 0.f) ? 0.f : (1.f / (1.f + __expf(-acc)));
            out[(size_t)Bn * KMn     + (size_t)row * KMn + c] = s;
            out[(size_t)Bn * KMn * 2 + (size_t)row * KMn + c] = s * g_cscores[row * KMn + c];
        }
    }
}

extern "C" void kernel_launch(void* const* d_in, const int* in_sizes, int n_in,
                              void* d_out, int out_size) {
    // Bind inputs by element count (robust to metadata ordering):
    //   meta_logits  128*65536   = 8388608   f32
    //   h_c          128*512     = 65536     f32
    //   embed_table  670001*512  = 343040512 f32
    //   label_clusters 65536*16  = 1048576   i32 (jax x64 disabled -> int32)
    const float* meta = nullptr;
    const float* hc = nullptr;
    const float* table = nullptr;
    const int* clusters = nullptr;
    for (int i = 0; i < n_in; i++) {
        switch (in_sizes[i]) {
            case 8388608:   meta     = (const float*)d_in[i]; break;
            case 65536:     hc       = (const float*)d_in[i]; break;
            case 343040512: table    = (const float*)d_in[i]; break;
            case 1048576:   clusters = (const int*)d_in[i];   break;
            default: break; // topk scalar etc.
        }
    }
    float* out = (float*)d_out; // 3 * 128 * 3200 f32: [cands | cand_scores | product]

    topk_kernel<<<Bn, 1024>>>(meta);
    expand_kernel<<<Bn, 1024>>>(clusters, out);
    dim3 g3(KMn / 32, Bn);
    score_kernel<<<g3, 256>>>(hc, table, out);
}